// round 5
// baseline (speedup 1.0000x reference)
#include <cuda_runtime.h>
#include <math.h>

// ---------------- static scratch (no allocations allowed) ----------------
__device__ float g_conv[(size_t)800 * 84 * 84 * 64];   // conv output scratch (max layer)
__device__ float g_p1[(size_t)800 * 42 * 42 * 64];
__device__ float g_p2[(size_t)800 * 21 * 21 * 64];
__device__ float g_p3[(size_t)800 * 10 * 10 * 64];
__device__ float g_emb[(size_t)800 * 1600];
__device__ float g_xw[(size_t)2 * 800 * 128];
__device__ float g_spart[64 * 25 * 64 * 2];            // per-block stats partials
__device__ float g_stats[25 * 64 * 2];
__device__ float g_outs[(size_t)5 * 21 * 32 * 64];

__device__ __forceinline__ float sigf(float x) { return 1.f / (1.f + expf(-x)); }

// ---------------- conv1: 3->64, 84x84 SAME ----------------
// grid (21 strips, 800 imgs), 256 threads. Strip = 4 output rows.
__global__ void __launch_bounds__(256, 4)
k_conv1(const float* __restrict__ xs, const float* __restrict__ xq,
        const float* __restrict__ w, const float* __restrict__ bias) {
    __shared__ float s_in[6 * 86 * 3];
    __shared__ float s_w[27 * 64];
    const int tid = threadIdx.x;
    const int im = blockIdx.y;
    const int strip = blockIdx.x;
    const int g = im >> 5, n = im & 31;
    const float* src = (g < 20) ? xs + (size_t)(n * 20 + g) * (84 * 84 * 3)
                                : xq + (size_t)(n * 5 + (g - 20)) * (84 * 84 * 3);

    for (int i = tid; i < 27 * 64; i += 256) s_w[i] = w[i];
    for (int i = tid; i < 6 * 86 * 3; i += 256) {
        int ci = i % 3; int c = (i / 3) % 86; int r = i / (3 * 86);
        int gy = strip * 4 - 1 + r, gx = c - 1;
        float v = 0.f;
        if (gy >= 0 && gy < 84 && gx >= 0 && gx < 84) v = src[(gy * 84 + gx) * 3 + ci];
        s_in[i] = v;
    }
    __syncthreads();

    const int cg = tid & 3;    // cout group of 16
    const int ppb = tid >> 2;  // pixel-pair base 0..63
    float bb[16];
#pragma unroll
    for (int j = 0; j < 16; ++j) bb[j] = bias[cg * 16 + j];

    for (int it = 0; it < 3; ++it) {
        int pp = ppb + it * 64;
        if (pp < 168) {
            int prow = pp / 42;
            int col0 = (pp % 42) * 2;
            float acc0[16], acc1[16];
#pragma unroll
            for (int j = 0; j < 16; ++j) { acc0[j] = bb[j]; acc1[j] = bb[j]; }
#pragma unroll
            for (int k = 0; k < 27; ++k) {
                int ky = k / 9, kx = (k % 9) / 3, ci = k % 3;
                float a0 = s_in[((prow + ky) * 86 + (col0 + kx)) * 3 + ci];
                float a1 = s_in[((prow + ky) * 86 + (col0 + 1 + kx)) * 3 + ci];
                const float* wr = &s_w[k * 64 + cg * 16];
#pragma unroll
                for (int j4 = 0; j4 < 4; ++j4) {
                    float4 wv = *(const float4*)(wr + j4 * 4);
                    acc0[j4 * 4 + 0] += a0 * wv.x; acc1[j4 * 4 + 0] += a1 * wv.x;
                    acc0[j4 * 4 + 1] += a0 * wv.y; acc1[j4 * 4 + 1] += a1 * wv.y;
                    acc0[j4 * 4 + 2] += a0 * wv.z; acc1[j4 * 4 + 2] += a1 * wv.z;
                    acc0[j4 * 4 + 3] += a0 * wv.w; acc1[j4 * 4 + 3] += a1 * wv.w;
                }
            }
            int oy = strip * 4 + prow;
            size_t base = ((size_t)im * 7056 + (size_t)oy * 84 + col0) * 64 + cg * 16;
#pragma unroll
            for (int j4 = 0; j4 < 4; ++j4) {
                *(float4*)&g_conv[base + j4 * 4] =
                    make_float4(acc0[j4*4], acc0[j4*4+1], acc0[j4*4+2], acc0[j4*4+3]);
                *(float4*)&g_conv[base + 64 + j4 * 4] =
                    make_float4(acc1[j4*4], acc1[j4*4+1], acc1[j4*4+2], acc1[j4*4+3]);
            }
        }
    }
}

// ---------------- conv 64->64, HxH SAME ----------------
// grid (tiles, 800), 128 threads. Tile 8x8 px x 64 cout; per thread 4px x 8cout.
__global__ void __launch_bounds__(128, 1)
k_conv64(const float* __restrict__ in, float* __restrict__ out,
         const float* __restrict__ w, const float* __restrict__ bias,
         int H, int tilesX) {
    __shared__ float s_in[10 * 10 * 16];
    __shared__ float s_w[9 * 16 * 64];
    const int tid = threadIdx.x;
    const int im = blockIdx.y;
    const int tile = blockIdx.x;
    const int tx0 = (tile % tilesX) * 8, ty0 = (tile / tilesX) * 8;
    const int HW = H * H;
    const int tp = tid & 15, tc = tid >> 4;
    const int prow = tp >> 1, col0 = (tp & 1) * 4;
    const float* imbase = in + (size_t)im * HW * 64;

    float acc[4][8];
#pragma unroll
    for (int j = 0; j < 8; ++j) {
        float bb = bias[tc * 8 + j];
#pragma unroll
        for (int i = 0; i < 4; ++i) acc[i][j] = bb;
    }

    for (int cc = 0; cc < 4; ++cc) {
        __syncthreads();
        for (int i = tid; i < 1600; i += 128) {
            int ci = i & 15, c = (i >> 4) % 10, r = i / 160;
            int gy = ty0 + r - 1, gx = tx0 + c - 1;
            float v = 0.f;
            if (gy >= 0 && gy < H && gx >= 0 && gx < H)
                v = imbase[(size_t)(gy * H + gx) * 64 + cc * 16 + ci];
            s_in[i] = v;
        }
        for (int i4 = tid; i4 < 2304; i4 += 128) {
            int co4 = i4 & 15, ci = (i4 >> 4) & 15, k9 = i4 >> 8;
            *(float4*)&s_w[i4 * 4] =
                *(const float4*)&w[((size_t)(k9 * 64 + cc * 16 + ci)) * 64 + co4 * 4];
        }
        __syncthreads();

#pragma unroll 1
        for (int k9 = 0; k9 < 9; ++k9) {
            int ky = k9 / 3, kx = k9 - ky * 3;
            const float* sr = &s_in[((prow + ky) * 10 + col0 + kx) * 16];
            const float* wr = &s_w[k9 * 1024 + tc * 8];
#pragma unroll
            for (int c4 = 0; c4 < 4; ++c4) {
                float as[4][4];
#pragma unroll
                for (int i = 0; i < 4; ++i) {
                    float4 t = *(const float4*)(sr + i * 16 + c4 * 4);
                    as[i][0] = t.x; as[i][1] = t.y; as[i][2] = t.z; as[i][3] = t.w;
                }
#pragma unroll
                for (int cj = 0; cj < 4; ++cj) {
                    const float* wp = wr + (c4 * 4 + cj) * 64;
                    float4 w0 = *(const float4*)wp;
                    float4 w1 = *(const float4*)(wp + 4);
#pragma unroll
                    for (int i = 0; i < 4; ++i) {
                        float a = as[i][cj];
                        acc[i][0] += a * w0.x; acc[i][1] += a * w0.y;
                        acc[i][2] += a * w0.z; acc[i][3] += a * w0.w;
                        acc[i][4] += a * w1.x; acc[i][5] += a * w1.y;
                        acc[i][6] += a * w1.z; acc[i][7] += a * w1.w;
                    }
                }
            }
        }
    }

    int oy = ty0 + prow;
    if (oy < H) {
#pragma unroll
        for (int i = 0; i < 4; ++i) {
            int ox = tx0 + col0 + i;
            if (ox < H) {
                float* o = &out[((size_t)im * HW + (size_t)oy * H + ox) * 64 + tc * 8];
                *(float4*)o       = make_float4(acc[i][0], acc[i][1], acc[i][2], acc[i][3]);
                *(float4*)(o + 4) = make_float4(acc[i][4], acc[i][5], acc[i][6], acc[i][7]);
            }
        }
    }
}

// stats pass 1: per-block partials. grid (64, 25 groups), 256 threads.
__global__ void k_stats(const float* __restrict__ conv, int HW) {
    __shared__ float ss[256], sq[256];
    int g = blockIdx.y, blk = blockIdx.x, tid = threadIdx.x;
    int c = tid & 63, l = tid >> 6;
    int P = 32 * HW;
    float s = 0.f, q = 0.f;
    for (int p = blk * 4 + l; p < P; p += 64 * 4) {
        float v = conv[((size_t)g * P + p) * 64 + c];
        s += v; q += v * v;
    }
    ss[tid] = s; sq[tid] = q;
    __syncthreads();
    if (tid < 64) {
        s = ss[tid] + ss[tid + 64] + ss[tid + 128] + ss[tid + 192];
        q = sq[tid] + sq[tid + 64] + sq[tid + 128] + sq[tid + 192];
        g_spart[((size_t)blk * 25 + g) * 128 + tid * 2]     = s;
        g_spart[((size_t)blk * 25 + g) * 128 + tid * 2 + 1] = q;
    }
}

// stats pass 2: fixed-order reduction of 64 partials. 1600 (g,c) pairs.
__global__ void k_sreduce() {
    int i = blockIdx.x * 256 + threadIdx.x;   // i = g*64+c
    if (i >= 1600) return;
    int g = i >> 6, c = i & 63;
    float s = 0.f, q = 0.f;
#pragma unroll 4
    for (int blk = 0; blk < 64; ++blk) {
        s += g_spart[((size_t)blk * 25 + g) * 128 + c * 2];
        q += g_spart[((size_t)blk * 25 + g) * 128 + c * 2 + 1];
    }
    g_stats[i * 2] = s;
    g_stats[i * 2 + 1] = q;
}

// BN + relu + 2x2/2 maxpool. total = 800*Hout*Hout*64
__global__ void k_bnpool(const float* __restrict__ conv, float* __restrict__ out,
                         const float* __restrict__ gam, const float* __restrict__ bet,
                         int Hin, int Hout, float invcnt, int total) {
    int i = blockIdx.x * 256 + threadIdx.x;
    if (i >= total) return;
    int c = i & 63;
    int t = i >> 6;
    int xo = t % Hout; t /= Hout;
    int yo = t % Hout;
    int im = t / Hout;
    int g = im >> 5;
    float s = g_stats[(g * 64 + c) * 2];
    float qq = g_stats[(g * 64 + c) * 2 + 1];
    float mean = s * invcnt;
    float var = qq * invcnt - mean * mean;
    float scale = gam[c] * rsqrtf(var + 1e-3f);
    float shift = bet[c] - mean * scale;
    size_t base = (((size_t)im * Hin + 2 * yo) * Hin + 2 * xo) * 64 + c;
    float v00 = fmaxf(conv[base] * scale + shift, 0.f);
    float v01 = fmaxf(conv[base + 64] * scale + shift, 0.f);
    float v10 = fmaxf(conv[base + (size_t)Hin * 64] * scale + shift, 0.f);
    float v11 = fmaxf(conv[base + (size_t)Hin * 64 + 64] * scale + shift, 0.f);
    out[i] = fmaxf(fmaxf(v00, v01), fmaxf(v10, v11));
}

// x @ Wx + b, both directions. grid (200, 2), 128 threads, 4 images/block.
__global__ void k_xw(const float* __restrict__ fk, const float* __restrict__ fb,
                     const float* __restrict__ bk, const float* __restrict__ bb) {
    __shared__ float es[4 * 1600];
    int tid = threadIdx.x, dir = blockIdx.y, im0 = blockIdx.x * 4;
    const float* W = dir ? bk : fk;
    const float* B = dir ? bb : fb;
    for (int i = tid; i < 6400; i += 128) es[i] = g_emb[(size_t)im0 * 1600 + i];
    __syncthreads();
    float a0 = 0.f, a1 = 0.f, a2 = 0.f, a3 = 0.f;
#pragma unroll 4
    for (int k = 0; k < 1600; ++k) {
        float wv = W[(size_t)k * 128 + tid];
        a0 += es[k] * wv;
        a1 += es[1600 + k] * wv;
        a2 += es[3200 + k] * wv;
        a3 += es[4800 + k] * wv;
    }
    float bv = B[tid];
    g_xw[((size_t)dir * 800 + im0 + 0) * 128 + tid] = a0 + bv;
    g_xw[((size_t)dir * 800 + im0 + 1) * 128 + tid] = a1 + bv;
    g_xw[((size_t)dir * 800 + im0 + 2) * 128 + tid] = a2 + bv;
    g_xw[((size_t)dir * 800 + im0 + 3) * 128 + tid] = a3 + bv;
}

// BiLSTM over the 32-step episode axis. grid (5 queries, 2 dirs), 128 threads.
__global__ void k_lstm(const float* __restrict__ fr, const float* __restrict__ br) {
    __shared__ float wh[32 * 128];
    __shared__ float hs[672], cs[672], zs[21 * 128];
    int q = blockIdx.x, dir = blockIdx.y, tid = threadIdx.x;
    const float* R = dir ? br : fr;
    for (int i = tid; i < 4096; i += 128) wh[i] = R[i];
    for (int i = tid; i < 672; i += 128) { hs[i] = 0.f; cs[i] = 0.f; }
    __syncthreads();

    for (int t = 0; t < 32; ++t) {
        int e = dir ? 31 - t : t;
#pragma unroll 3
        for (int j = 0; j < 21; ++j) {
            int gj = (j < 20) ? j : 20 + q;
            float z = g_xw[((size_t)dir * 800 + gj * 32 + e) * 128 + tid];
            float z1 = 0.f;
#pragma unroll
            for (int k = 0; k < 32; k += 2) {
                z  += hs[j * 32 + k]     * wh[k * 128 + tid];
                z1 += hs[j * 32 + k + 1] * wh[(k + 1) * 128 + tid];
            }
            zs[j * 128 + tid] = z + z1;
        }
        __syncthreads();
        for (int idx = tid; idx < 672; idx += 128) {
            int j = idx >> 5, u = idx & 31;
            float zi = zs[j * 128 + u];
            float zf = zs[j * 128 + 32 + u];
            float zg = zs[j * 128 + 64 + u];
            float zo = zs[j * 128 + 96 + u];
            float c = sigf(zf) * cs[idx] + sigf(zi) * tanhf(zg);
            float h = sigf(zo) * tanhf(c);
            cs[idx] = c; hs[idx] = h;
            g_outs[(((size_t)q * 21 + j) * 32 + e) * 64 + dir * 32 + u] = h;
        }
        __syncthreads();
    }
}

// Epilogue: cosine-attention, softmax, preds, CE, acc. Single block, deterministic.
__global__ void k_final(const int* __restrict__ ys, const int* __restrict__ yq,
                        float* __restrict__ out) {
    __shared__ float s_ce[160];
    __shared__ float s_eq[160];
    int t = threadIdx.x;
    if (t < 160) {
        int q = t / 32, b = t % 32;
        const float* qp = &g_outs[(((size_t)q * 21 + 20) * 32 + b) * 64];
        float val[20];
        for (int s = 0; s < 20; ++s) {
            const float* sp = &g_outs[(((size_t)q * 21 + s) * 32 + b) * 64];
            float dot = 0.f, ssq = 0.f;
            for (int d = 0; d < 64; ++d) {
                float sv = sp[d];
                dot += qp[d] * sv;
                ssq += sv * sv;
            }
            val[s] = dot * rsqrtf(fmaxf(ssq, 1e-10f));
        }
        float m = -1e30f;
        for (int s = 0; s < 20; ++s) m = fmaxf(m, val[s]);
        float sum = 0.f;
        for (int s = 0; s < 20; ++s) { val[s] = expf(val[s] - m); sum += val[s]; }
        float inv = 1.f / sum;

        float preds[20];
        for (int w = 0; w < 20; ++w) preds[w] = 0.f;
        for (int s = 0; s < 20; ++s) preds[ys[b * 20 + s]] += val[s] * inv;

        int lbl = yq[b * 5 + q];
        float p = fminf(fmaxf(preds[lbl], 1e-7f), 1.f - 1e-7f);
        s_ce[t] = -logf(p);

        int am = 0; float bv = preds[0];
        for (int w = 1; w < 20; ++w) if (preds[w] > bv) { bv = preds[w]; am = w; }
        s_eq[t] = (am == lbl) ? 1.f : 0.f;
    }
    __syncthreads();
    if (t < 32) {
        float ce = 0.f;
        for (int q = 0; q < 5; ++q) ce += s_ce[q * 32 + t];
        out[t] = ce * 0.2f;
    }
    if (t == 32) {
        float a = 0.f;
        for (int i = 0; i < 160; ++i) a += s_eq[i];
        out[32] = a * (1.f / 160.f);
    }
}

extern "C" void kernel_launch(void* const* d_in, const int* in_sizes, int n_in,
                              void* d_out, int out_size) {
    const float* xs  = (const float*)d_in[0];
    const int*   ysup= (const int*)  d_in[1];
    const float* xq  = (const float*)d_in[2];
    const int*   yqry= (const int*)  d_in[3];
    const float* k1 = (const float*)d_in[4];
    const float* b1 = (const float*)d_in[5];
    const float* g1 = (const float*)d_in[6];
    const float* be1= (const float*)d_in[7];
    const float* k2 = (const float*)d_in[8];
    const float* b2 = (const float*)d_in[9];
    const float* g2 = (const float*)d_in[10];
    const float* be2= (const float*)d_in[11];
    const float* k3 = (const float*)d_in[12];
    const float* b3 = (const float*)d_in[13];
    const float* g3 = (const float*)d_in[14];
    const float* be3= (const float*)d_in[15];
    const float* k4 = (const float*)d_in[16];
    const float* b4 = (const float*)d_in[17];
    const float* g4 = (const float*)d_in[18];
    const float* be4= (const float*)d_in[19];
    const float* fk = (const float*)d_in[20];
    const float* fr = (const float*)d_in[21];
    const float* fb = (const float*)d_in[22];
    const float* bk = (const float*)d_in[23];
    const float* br = (const float*)d_in[24];
    const float* bb = (const float*)d_in[25];
    float* out = (float*)d_out;

    float* cv; cudaGetSymbolAddress((void**)&cv, g_conv);
    float* p1; cudaGetSymbolAddress((void**)&p1, g_p1);
    float* p2; cudaGetSymbolAddress((void**)&p2, g_p2);
    float* p3; cudaGetSymbolAddress((void**)&p3, g_p3);
    float* em; cudaGetSymbolAddress((void**)&em, g_emb);

    // ---- layer 1: 84x84, 3->64 ----
    k_conv1<<<dim3(21, 800), 256>>>(xs, xq, k1, b1);
    k_stats<<<dim3(64, 25), 256>>>(cv, 84 * 84);
    k_sreduce<<<7, 256>>>();
    k_bnpool<<<(800*42*42*64 + 255) / 256, 256>>>(cv, p1, g1, be1, 84, 42,
                                                  1.f / (32.f * 7056.f), 800*42*42*64);
    // ---- layer 2: 42x42 ----
    k_conv64<<<dim3(36, 800), 128>>>(p1, cv, k2, b2, 42, 6);
    k_stats<<<dim3(64, 25), 256>>>(cv, 42 * 42);
    k_sreduce<<<7, 256>>>();
    k_bnpool<<<(800*21*21*64 + 255) / 256, 256>>>(cv, p2, g2, be2, 42, 21,
                                                  1.f / (32.f * 1764.f), 800*21*21*64);
    // ---- layer 3: 21x21 ----
    k_conv64<<<dim3(9, 800), 128>>>(p2, cv, k3, b3, 21, 3);
    k_stats<<<dim3(64, 25), 256>>>(cv, 21 * 21);
    k_sreduce<<<7, 256>>>();
    k_bnpool<<<(800*10*10*64 + 255) / 256, 256>>>(cv, p3, g3, be3, 21, 10,
                                                  1.f / (32.f * 441.f), 800*10*10*64);
    // ---- layer 4: 10x10 ----
    k_conv64<<<dim3(4, 800), 128>>>(p3, cv, k4, b4, 10, 2);
    k_stats<<<dim3(64, 25), 256>>>(cv, 10 * 10);
    k_sreduce<<<7, 256>>>();
    k_bnpool<<<(800*5*5*64 + 255) / 256, 256>>>(cv, em, g4, be4, 10, 5,
                                                1.f / (32.f * 100.f), 800*5*5*64);
    // ---- LSTM input GEMM, BiLSTM, epilogue ----
    k_xw<<<dim3(200, 2), 128>>>(fk, fb, bk, bb);
    k_lstm<<<dim3(5, 2), 128>>>(fr, br);
    k_final<<<1, 192>>>(ysup, yqry, out);
}